// round 5
// baseline (speedup 1.0000x reference)
#include <cuda_runtime.h>
#include <cuda_bf16.h>

#define N_NODES 100000
#define N_EDGES 3200000
#define DIM 64
#define N_LAYERS 3
#define OUT_DIM (4 * DIM)

#define SCAN_B 1024
#define SCAN_NBLK ((N_NODES + SCAN_B - 1) / SCAN_B)   // 98
#define SPAD 68

// ---------------------------------------------------------------------------
// Scratch (allocation-free contract: __device__ globals)
// ---------------------------------------------------------------------------
__device__ int  g_count[N_NODES];            // per-dst degree histogram
__device__ int  g_cursor[N_NODES];           // running cursors for reorder
__device__ int  g_rowptr[N_NODES + 1];       // CSR offsets (dst-sorted)
__device__ int  g_blocksums[128];            // scan block sums
__device__ int2 g_sorted[N_EDGES];           // packed {src, a_bits}, dst-sorted

// ---------------------------------------------------------------------------
// Generic zero (float4-vectorized, grid-stride)
// ---------------------------------------------------------------------------
__global__ void zero_kernel(float4* __restrict__ p, int n4) {
    int i = blockIdx.x * blockDim.x + threadIdx.x;
    const float4 z = make_float4(0.f, 0.f, 0.f, 0.f);
    for (; i < n4; i += gridDim.x * blockDim.x) p[i] = z;
}

// ---------------------------------------------------------------------------
// Copy x into out[:, 0:64]
// ---------------------------------------------------------------------------
__global__ void copy_x_kernel(const float4* __restrict__ x4, float4* __restrict__ out4) {
    int i = blockIdx.x * blockDim.x + threadIdx.x;
    if (i >= N_NODES * (DIM / 4)) return;
    int n = i >> 4;
    int c = i & 15;
    out4[n * (OUT_DIM / 4) + c] = x4[i];
}

// ---------------------------------------------------------------------------
// Counting sort by dst (one-time)
// ---------------------------------------------------------------------------
__global__ void hist_kernel(const int* __restrict__ dst) {
    int e = blockIdx.x * blockDim.x + threadIdx.x;
    if (e >= N_EDGES) return;
    atomicAdd(&g_count[dst[e]], 1);
}

__global__ __launch_bounds__(SCAN_B)
void scan_sum_kernel() {
    int i = blockIdx.x * SCAN_B + threadIdx.x;
    int v = (i < N_NODES) ? g_count[i] : 0;
    int lane = threadIdx.x & 31, w = threadIdx.x >> 5;
    #pragma unroll
    for (int d = 16; d; d >>= 1) v += __shfl_down_sync(~0u, v, d);
    __shared__ int s[32];
    if (lane == 0) s[w] = v;
    __syncthreads();
    if (w == 0) {
        v = s[lane];
        #pragma unroll
        for (int d = 16; d; d >>= 1) v += __shfl_down_sync(~0u, v, d);
        if (lane == 0) g_blocksums[blockIdx.x] = v;
    }
}

__global__ void scan_tops_kernel() {
    __shared__ int s[128];
    int tid = threadIdx.x;
    int v = (tid < SCAN_NBLK) ? g_blocksums[tid] : 0;
    s[tid] = v;
    __syncthreads();
    for (int off = 1; off < 128; off <<= 1) {
        int t = (tid >= off) ? s[tid - off] : 0;
        __syncthreads();
        s[tid] += t;
        __syncthreads();
    }
    if (tid < SCAN_NBLK) g_blocksums[tid] = s[tid] - v;   // exclusive
    if (tid == 0) g_rowptr[N_NODES] = N_EDGES;
}

__global__ __launch_bounds__(SCAN_B)
void scan_write_kernel() {
    int i = blockIdx.x * SCAN_B + threadIdx.x;
    int v = (i < N_NODES) ? g_count[i] : 0;
    int lane = threadIdx.x & 31, w = threadIdx.x >> 5;
    int inc = v;
    #pragma unroll
    for (int d = 1; d < 32; d <<= 1) {
        int t = __shfl_up_sync(~0u, inc, d);
        if (lane >= d) inc += t;
    }
    __shared__ int ws[32];
    if (lane == 31) ws[w] = inc;
    __syncthreads();
    if (w == 0) {
        int t = ws[lane];
        #pragma unroll
        for (int d = 1; d < 32; d <<= 1) {
            int u = __shfl_up_sync(~0u, t, d);
            if (lane >= d) t += u;
        }
        ws[lane] = t;
    }
    __syncthreads();
    int warpOff = (w == 0) ? 0 : ws[w - 1];
    int excl = inc - v + warpOff + g_blocksums[blockIdx.x];
    if (i < N_NODES) { g_cursor[i] = excl; g_rowptr[i] = excl; }
}

__global__ void reorder_kernel(const int* __restrict__ src,
                               const int* __restrict__ dst,
                               const float* __restrict__ a) {
    int e = blockIdx.x * blockDim.x + threadIdx.x;
    if (e >= N_EDGES) return;
    int d = dst[e];
    int pos = atomicAdd(&g_cursor[d], 1);
    int2 rec;
    rec.x = src[e];
    rec.y = __float_as_int(a[e]);
    g_sorted[pos] = rec;
}

// ---------------------------------------------------------------------------
// Fused layer kernel (edge-balanced):
//   Block owns 64 dst nodes -> one CONTIGUOUS sorted-edge range. Split range
//   into 16 equal chunks; each half-warp walks its chunk with unroll-4 MLP,
//   register-accumulates per dst segment, flushes via smem atomicAdd into
//   transposed hn staging. Then s/p transform + register-tiled dual GEMM.
// ---------------------------------------------------------------------------
__device__ __forceinline__ float lrelu(float v) {
    return v > 0.f ? v : 0.01f * v;
}

extern __shared__ float dyn_smem[];

__global__ __launch_bounds__(256)
void fused_layer_kernel(const float4* __restrict__ hin, int strideF4,
                        const float* __restrict__ W1, const float* __restrict__ b1,
                        const float* __restrict__ W2, const float* __restrict__ b2,
                        float* __restrict__ outSeg) {
    float* sW1 = dyn_smem;                 // [64*64]
    float* sW2 = sW1 + DIM * DIM;          // [64*64]
    float* sS  = sW2 + DIM * DIM;          // [64][SPAD] k-major (s staging)
    float* sP  = sS + DIM * SPAD;          // [64][SPAD] hn accum -> p staging
    int*   sRow = (int*)(sP + DIM * SPAD); // [65] rowptr slice

    int t = threadIdx.x;
    int base = blockIdx.x * 64;

    // Zero hn accumulator (sP) + load weights + rowptr slice
    {
        float4* zp = (float4*)sP;
        #pragma unroll
        for (int i = 0; i < 5; i++) {
            int idx = t + i * 256;
            if (idx < DIM * SPAD / 4) zp[idx] = make_float4(0.f, 0.f, 0.f, 0.f);
        }
        const float4* w1v = (const float4*)W1;
        const float4* w2v = (const float4*)W2;
        float4* s1v = (float4*)sW1;
        float4* s2v = (float4*)sW2;
        #pragma unroll
        for (int i = 0; i < 4; i++) {
            s1v[t + i * 256] = w1v[t + i * 256];
            s2v[t + i * 256] = w2v[t + i * 256];
        }
        if (t < 65) {
            int n = base + t;
            sRow[t] = g_rowptr[n < N_NODES ? n : N_NODES];
        }
    }
    __syncthreads();

    int hw = t >> 4;        // half-warp id 0..15
    int lane = t & 15;      // float4-column within a 64-float row
    int k0 = lane * 4;

    // ---- Edge-balanced gather ----
    {
        int e0 = sRow[0];
        int eTot = sRow[64] - e0;
        int chunk = (eTot + 15) >> 4;
        int ce = e0 + hw * chunk;
        int cend = ce + chunk;
        if (cend > e0 + eTot) cend = e0 + eTot;

        if (ce < cend) {
            // binary search: largest cur in [0,63] with sRow[cur] <= ce
            int lo = 0, hi = 63;
            while (lo < hi) {
                int mid = (lo + hi + 1) >> 1;
                lo = (sRow[mid] <= ce) ? mid : lo;
                hi = (sRow[mid] <= ce) ? hi : mid - 1;
            }
            int cur = lo;
            int segEnd = sRow[cur + 1];
            float4 acc = make_float4(0.f, 0.f, 0.f, 0.f);

            int e = ce;
            while (e < cend) {
                int m = cend - e; if (m > 4) m = 4;
                int2 r[4];
                float4 v[4];
                #pragma unroll
                for (int j = 0; j < 4; j++)
                    if (j < m) r[j] = g_sorted[e + j];
                #pragma unroll
                for (int j = 0; j < 4; j++)
                    if (j < m) v[j] = hin[(size_t)r[j].x * strideF4 + lane];
                #pragma unroll
                for (int j = 0; j < 4; j++) {
                    if (j < m) {
                        int eg = e + j;
                        if (eg >= segEnd) {
                            atomicAdd(&sP[(k0 + 0) * SPAD + cur], acc.x);
                            atomicAdd(&sP[(k0 + 1) * SPAD + cur], acc.y);
                            atomicAdd(&sP[(k0 + 2) * SPAD + cur], acc.z);
                            atomicAdd(&sP[(k0 + 3) * SPAD + cur], acc.w);
                            acc = make_float4(0.f, 0.f, 0.f, 0.f);
                            do { cur++; segEnd = sRow[cur + 1]; } while (segEnd <= eg);
                        }
                        float ae = __int_as_float(r[j].y);
                        acc.x = fmaf(ae, v[j].x, acc.x);
                        acc.y = fmaf(ae, v[j].y, acc.y);
                        acc.z = fmaf(ae, v[j].z, acc.z);
                        acc.w = fmaf(ae, v[j].w, acc.w);
                    }
                }
                e += 4;
            }
            atomicAdd(&sP[(k0 + 0) * SPAD + cur], acc.x);
            atomicAdd(&sP[(k0 + 1) * SPAD + cur], acc.y);
            atomicAdd(&sP[(k0 + 2) * SPAD + cur], acc.z);
            atomicAdd(&sP[(k0 + 3) * SPAD + cur], acc.w);
        }
    }
    __syncthreads();

    // ---- Transform: sS = h + hn, sP = h * hn (in place, transposed) ----
    #pragma unroll
    for (int i = 0; i < 4; i++) {
        int nloc = hw * 4 + i;
        int node = base + nloc;
        float4 hv = make_float4(0.f, 0.f, 0.f, 0.f);
        if (node < N_NODES) hv = hin[(size_t)node * strideF4 + lane];
        float hva[4] = {hv.x, hv.y, hv.z, hv.w};
        #pragma unroll
        for (int j = 0; j < 4; j++) {
            int idx = (k0 + j) * SPAD + nloc;
            float hnv = sP[idx];
            sS[idx] = hva[j] + hnv;
            sP[idx] = hva[j] * hnv;
        }
    }
    __syncthreads();

    // ---- Register-tiled dual GEMM: 4 nodes x 4 cols per thread ----
    int m0 = (t & 15) * 4;
    int c0 = (t >> 4) * 4;

    float acc1[4][4];
    float acc2[4][4];
    #pragma unroll
    for (int i = 0; i < 4; i++)
        #pragma unroll
        for (int j = 0; j < 4; j++) { acc1[i][j] = 0.f; acc2[i][j] = 0.f; }

    #pragma unroll 4
    for (int k = 0; k < DIM; k++) {
        float4 sv = *(const float4*)(sS + k * SPAD + m0);
        float4 pv = *(const float4*)(sP + k * SPAD + m0);
        float4 w1 = *(const float4*)(sW1 + k * DIM + c0);
        float4 w2 = *(const float4*)(sW2 + k * DIM + c0);
        float sm[4] = {sv.x, sv.y, sv.z, sv.w};
        float pm[4] = {pv.x, pv.y, pv.z, pv.w};
        float w1a[4] = {w1.x, w1.y, w1.z, w1.w};
        float w2a[4] = {w2.x, w2.y, w2.z, w2.w};
        #pragma unroll
        for (int i = 0; i < 4; i++) {
            #pragma unroll
            for (int j = 0; j < 4; j++) {
                acc1[i][j] = fmaf(sm[i], w1a[j], acc1[i][j]);
                acc2[i][j] = fmaf(pm[i], w2a[j], acc2[i][j]);
            }
        }
    }

    float4 rb1 = *(const float4*)(b1 + c0);
    float4 rb2 = *(const float4*)(b2 + c0);
    float b1a[4] = {rb1.x, rb1.y, rb1.z, rb1.w};
    float b2a[4] = {rb2.x, rb2.y, rb2.z, rb2.w};

    #pragma unroll
    for (int i = 0; i < 4; i++) {
        int node = base + m0 + i;
        if (node >= N_NODES) break;
        float4 r;
        float* rp = (float*)&r;
        #pragma unroll
        for (int j = 0; j < 4; j++)
            rp[j] = lrelu(acc1[i][j] + b1a[j]) + lrelu(acc2[i][j] + b2a[j]);
        *(float4*)(outSeg + (size_t)node * OUT_DIM + c0) = r;
    }
}

// ---------------------------------------------------------------------------
// Launch
// ---------------------------------------------------------------------------
extern "C" void kernel_launch(void* const* d_in, const int* in_sizes, int n_in,
                              void* d_out, int out_size) {
    const float* x   = (const float*)d_in[0];
    const float* a   = (const float*)d_in[1];
    const float* W1s = (const float*)d_in[2];
    const float* b1s = (const float*)d_in[3];
    const float* W2s = (const float*)d_in[4];
    const float* b2s = (const float*)d_in[5];
    const int*   src = (const int*)d_in[6];
    const int*   dst = (const int*)d_in[7];
    float* out = (float*)d_out;

    int* cnt;
    cudaGetSymbolAddress((void**)&cnt, g_count);

    const int UPD_SMEM = (2 * DIM * DIM + 2 * DIM * SPAD + 68) * (int)sizeof(float);
    cudaFuncSetAttribute(fused_layer_kernel, cudaFuncAttributeMaxDynamicSharedMemorySize, UPD_SMEM);

    // out[:, 0:64] = x
    {
        int n4 = N_NODES * (DIM / 4);
        copy_x_kernel<<<(n4 + 255) / 256, 256>>>((const float4*)x, (float4*)out);
    }

    // ---- One-time counting sort of edges by dst (CSR + packed records) ----
    zero_kernel<<<128, 256>>>((float4*)cnt, N_NODES / 4);
    hist_kernel<<<(N_EDGES + 255) / 256, 256>>>(dst);
    scan_sum_kernel<<<SCAN_NBLK, SCAN_B>>>();
    scan_tops_kernel<<<1, 128>>>();
    scan_write_kernel<<<SCAN_NBLK, SCAN_B>>>();
    reorder_kernel<<<(N_EDGES + 255) / 256, 256>>>(src, dst, a);

    // ---- Layers: fully fused, h read in-place from output tensor ----
    int grid = (N_NODES + 63) / 64;
    for (int l = 0; l < N_LAYERS; l++) {
        const float4* hin;
        int strideF4;
        if (l == 0) { hin = (const float4*)x; strideF4 = DIM / 4; }
        else        { hin = (const float4*)out + (size_t)l * (DIM / 4); strideF4 = OUT_DIM / 4; }
        fused_layer_kernel<<<grid, 256, UPD_SMEM>>>(
            hin, strideF4,
            W1s + (size_t)l * DIM * DIM, b1s + (size_t)l * DIM,
            W2s + (size_t)l * DIM * DIM, b2s + (size_t)l * DIM,
            out + (size_t)(l + 1) * DIM);
    }
}

// round 6
// speedup vs baseline: 1.2414x; 1.2414x over previous
#include <cuda_runtime.h>
#include <cuda_bf16.h>

#define N_NODES 100000
#define N_EDGES 3200000
#define DIM 64
#define N_LAYERS 3
#define OUT_DIM (4 * DIM)

#define SCAN_B 1024
#define SCAN_NBLK ((N_NODES + SCAN_B - 1) / SCAN_B)   // 98
#define SPAD 68

// ---------------------------------------------------------------------------
// Scratch (allocation-free contract: __device__ globals)
// ---------------------------------------------------------------------------
__device__ int  g_count[N_NODES];            // per-dst degree histogram
__device__ int  g_cursor[N_NODES];           // running cursors for reorder
__device__ int  g_rowptr[N_NODES + 1];       // CSR offsets (dst-sorted)
__device__ int  g_blocksums[128];            // scan block sums
__device__ int2 g_sorted[N_EDGES];           // packed {src, a_bits}, dst-sorted

// ---------------------------------------------------------------------------
// Generic zero (float4-vectorized, grid-stride)
// ---------------------------------------------------------------------------
__global__ void zero_kernel(float4* __restrict__ p, int n4) {
    int i = blockIdx.x * blockDim.x + threadIdx.x;
    const float4 z = make_float4(0.f, 0.f, 0.f, 0.f);
    for (; i < n4; i += gridDim.x * blockDim.x) p[i] = z;
}

// ---------------------------------------------------------------------------
// Counting sort by dst (one-time)
// ---------------------------------------------------------------------------
__global__ void hist_kernel(const int* __restrict__ dst) {
    int e = blockIdx.x * blockDim.x + threadIdx.x;
    if (e >= N_EDGES) return;
    atomicAdd(&g_count[dst[e]], 1);
}

__global__ __launch_bounds__(SCAN_B)
void scan_sum_kernel() {
    int i = blockIdx.x * SCAN_B + threadIdx.x;
    int v = (i < N_NODES) ? g_count[i] : 0;
    int lane = threadIdx.x & 31, w = threadIdx.x >> 5;
    #pragma unroll
    for (int d = 16; d; d >>= 1) v += __shfl_down_sync(~0u, v, d);
    __shared__ int s[32];
    if (lane == 0) s[w] = v;
    __syncthreads();
    if (w == 0) {
        v = s[lane];
        #pragma unroll
        for (int d = 16; d; d >>= 1) v += __shfl_down_sync(~0u, v, d);
        if (lane == 0) g_blocksums[blockIdx.x] = v;
    }
}

__global__ void scan_tops_kernel() {
    __shared__ int s[128];
    int tid = threadIdx.x;
    int v = (tid < SCAN_NBLK) ? g_blocksums[tid] : 0;
    s[tid] = v;
    __syncthreads();
    for (int off = 1; off < 128; off <<= 1) {
        int t = (tid >= off) ? s[tid - off] : 0;
        __syncthreads();
        s[tid] += t;
        __syncthreads();
    }
    if (tid < SCAN_NBLK) g_blocksums[tid] = s[tid] - v;   // exclusive
    if (tid == 0) g_rowptr[N_NODES] = N_EDGES;
}

__global__ __launch_bounds__(SCAN_B)
void scan_write_kernel() {
    int i = blockIdx.x * SCAN_B + threadIdx.x;
    int v = (i < N_NODES) ? g_count[i] : 0;
    int lane = threadIdx.x & 31, w = threadIdx.x >> 5;
    int inc = v;
    #pragma unroll
    for (int d = 1; d < 32; d <<= 1) {
        int t = __shfl_up_sync(~0u, inc, d);
        if (lane >= d) inc += t;
    }
    __shared__ int ws[32];
    if (lane == 31) ws[w] = inc;
    __syncthreads();
    if (w == 0) {
        int t = ws[lane];
        #pragma unroll
        for (int d = 1; d < 32; d <<= 1) {
            int u = __shfl_up_sync(~0u, t, d);
            if (lane >= d) t += u;
        }
        ws[lane] = t;
    }
    __syncthreads();
    int warpOff = (w == 0) ? 0 : ws[w - 1];
    int excl = inc - v + warpOff + g_blocksums[blockIdx.x];
    if (i < N_NODES) { g_cursor[i] = excl; g_rowptr[i] = excl; }
}

__global__ void reorder_kernel(const int* __restrict__ src,
                               const int* __restrict__ dst,
                               const float* __restrict__ a) {
    int e = blockIdx.x * blockDim.x + threadIdx.x;
    if (e >= N_EDGES) return;
    int d = dst[e];
    int pos = atomicAdd(&g_cursor[d], 1);
    int2 rec;
    rec.x = src[e];
    rec.y = __float_as_int(a[e]);
    g_sorted[pos] = rec;
}

// ---------------------------------------------------------------------------
// Fused layer kernel (R4 structure, unroll-4 gather):
//   per block: own 64 dst nodes; 16 half-warps each gather+accumulate 4
//   nodes' edge segments (register h_n), stage s/p transposed in shared,
//   then register-tiled dual GEMM + bias + lrelu + sum.
//   If copySeg != nullptr (layer 0): also writes h rows to out[:,0:64].
// ---------------------------------------------------------------------------
__device__ __forceinline__ float lrelu(float v) {
    return v > 0.f ? v : 0.01f * v;
}

extern __shared__ float dyn_smem[];

__global__ __launch_bounds__(256)
void fused_layer_kernel(const float4* __restrict__ hin, int strideF4,
                        const float* __restrict__ W1, const float* __restrict__ b1,
                        const float* __restrict__ W2, const float* __restrict__ b2,
                        float* __restrict__ outSeg,
                        float* __restrict__ copySeg) {
    float* sW1 = dyn_smem;                 // [64*64]
    float* sW2 = sW1 + DIM * DIM;          // [64*64]
    float* sS  = sW2 + DIM * DIM;          // [64][SPAD] k-major
    float* sP  = sS + DIM * SPAD;          // [64][SPAD]

    int t = threadIdx.x;

    // Weights -> shared
    {
        const float4* w1v = (const float4*)W1;
        const float4* w2v = (const float4*)W2;
        float4* s1v = (float4*)sW1;
        float4* s2v = (float4*)sW2;
        #pragma unroll
        for (int i = 0; i < 4; i++) {
            s1v[t + i * 256] = w1v[t + i * 256];
            s2v[t + i * 256] = w2v[t + i * 256];
        }
    }

    int base = blockIdx.x * 64;
    int hw = t >> 4;        // half-warp id 0..15
    int lane = t & 15;      // float4-column within a 64-float row
    int k0 = lane * 4;

    // Gather + accumulate + stage. Each half-warp owns 4 consecutive nodes.
    #pragma unroll
    for (int i = 0; i < 4; i++) {
        int nloc = hw * 4 + i;
        int node = base + nloc;
        float4 acc = make_float4(0.f, 0.f, 0.f, 0.f);
        float4 hv  = make_float4(0.f, 0.f, 0.f, 0.f);
        if (node < N_NODES) {
            int e  = g_rowptr[node];
            int e1 = g_rowptr[node + 1];
            // steady loop: unroll-4, four independent gathers in flight
            for (; e + 3 < e1; e += 4) {
                int2 r0 = g_sorted[e];
                int2 r1 = g_sorted[e + 1];
                int2 r2 = g_sorted[e + 2];
                int2 r3 = g_sorted[e + 3];
                float4 v0 = hin[(size_t)r0.x * strideF4 + lane];
                float4 v1 = hin[(size_t)r1.x * strideF4 + lane];
                float4 v2 = hin[(size_t)r2.x * strideF4 + lane];
                float4 v3 = hin[(size_t)r3.x * strideF4 + lane];
                float a0 = __int_as_float(r0.y);
                float a1 = __int_as_float(r1.y);
                float a2 = __int_as_float(r2.y);
                float a3 = __int_as_float(r3.y);
                acc.x = fmaf(a0, v0.x, acc.x);
                acc.y = fmaf(a0, v0.y, acc.y);
                acc.z = fmaf(a0, v0.z, acc.z);
                acc.w = fmaf(a0, v0.w, acc.w);
                acc.x = fmaf(a1, v1.x, acc.x);
                acc.y = fmaf(a1, v1.y, acc.y);
                acc.z = fmaf(a1, v1.z, acc.z);
                acc.w = fmaf(a1, v1.w, acc.w);
                acc.x = fmaf(a2, v2.x, acc.x);
                acc.y = fmaf(a2, v2.y, acc.y);
                acc.z = fmaf(a2, v2.z, acc.z);
                acc.w = fmaf(a2, v2.w, acc.w);
                acc.x = fmaf(a3, v3.x, acc.x);
                acc.y = fmaf(a3, v3.y, acc.y);
                acc.z = fmaf(a3, v3.z, acc.z);
                acc.w = fmaf(a3, v3.w, acc.w);
            }
            for (; e < e1; e++) {
                int2 r0 = g_sorted[e];
                float4 v0 = hin[(size_t)r0.x * strideF4 + lane];
                float a0 = __int_as_float(r0.y);
                acc.x = fmaf(a0, v0.x, acc.x);
                acc.y = fmaf(a0, v0.y, acc.y);
                acc.z = fmaf(a0, v0.z, acc.z);
                acc.w = fmaf(a0, v0.w, acc.w);
            }
            hv = hin[(size_t)node * strideF4 + lane];
            if (copySeg != nullptr)
                *(float4*)(copySeg + (size_t)node * OUT_DIM + k0) = hv;
        }
        // stage s = h + hn, p = h * hn, transposed [k][node]
        sS[(k0 + 0) * SPAD + nloc] = hv.x + acc.x;
        sS[(k0 + 1) * SPAD + nloc] = hv.y + acc.y;
        sS[(k0 + 2) * SPAD + nloc] = hv.z + acc.z;
        sS[(k0 + 3) * SPAD + nloc] = hv.w + acc.w;
        sP[(k0 + 0) * SPAD + nloc] = hv.x * acc.x;
        sP[(k0 + 1) * SPAD + nloc] = hv.y * acc.y;
        sP[(k0 + 2) * SPAD + nloc] = hv.z * acc.z;
        sP[(k0 + 3) * SPAD + nloc] = hv.w * acc.w;
    }
    __syncthreads();

    // Register-tiled dual GEMM: 4 nodes x 4 cols per thread
    int m0 = (t & 15) * 4;
    int c0 = (t >> 4) * 4;

    float acc1[4][4];
    float acc2[4][4];
    #pragma unroll
    for (int i = 0; i < 4; i++)
        #pragma unroll
        for (int j = 0; j < 4; j++) { acc1[i][j] = 0.f; acc2[i][j] = 0.f; }

    #pragma unroll 4
    for (int k = 0; k < DIM; k++) {
        float4 sv = *(const float4*)(sS + k * SPAD + m0);
        float4 pv = *(const float4*)(sP + k * SPAD + m0);
        float4 w1 = *(const float4*)(sW1 + k * DIM + c0);
        float4 w2 = *(const float4*)(sW2 + k * DIM + c0);
        float sm[4] = {sv.x, sv.y, sv.z, sv.w};
        float pm[4] = {pv.x, pv.y, pv.z, pv.w};
        float w1a[4] = {w1.x, w1.y, w1.z, w1.w};
        float w2a[4] = {w2.x, w2.y, w2.z, w2.w};
        #pragma unroll
        for (int i = 0; i < 4; i++) {
            #pragma unroll
            for (int j = 0; j < 4; j++) {
                acc1[i][j] = fmaf(sm[i], w1a[j], acc1[i][j]);
                acc2[i][j] = fmaf(pm[i], w2a[j], acc2[i][j]);
            }
        }
    }

    float4 rb1 = *(const float4*)(b1 + c0);
    float4 rb2 = *(const float4*)(b2 + c0);
    float b1a[4] = {rb1.x, rb1.y, rb1.z, rb1.w};
    float b2a[4] = {rb2.x, rb2.y, rb2.z, rb2.w};

    #pragma unroll
    for (int i = 0; i < 4; i++) {
        int node = base + m0 + i;
        if (node >= N_NODES) break;
        float4 r;
        float* rp = (float*)&r;
        #pragma unroll
        for (int j = 0; j < 4; j++)
            rp[j] = lrelu(acc1[i][j] + b1a[j]) + lrelu(acc2[i][j] + b2a[j]);
        *(float4*)(outSeg + (size_t)node * OUT_DIM + c0) = r;
    }
}

// ---------------------------------------------------------------------------
// Launch
// ---------------------------------------------------------------------------
extern "C" void kernel_launch(void* const* d_in, const int* in_sizes, int n_in,
                              void* d_out, int out_size) {
    const float* x   = (const float*)d_in[0];
    const float* a   = (const float*)d_in[1];
    const float* W1s = (const float*)d_in[2];
    const float* b1s = (const float*)d_in[3];
    const float* W2s = (const float*)d_in[4];
    const float* b2s = (const float*)d_in[5];
    const int*   src = (const int*)d_in[6];
    const int*   dst = (const int*)d_in[7];
    float* out = (float*)d_out;

    int* cnt;
    cudaGetSymbolAddress((void**)&cnt, g_count);

    const int UPD_SMEM = (2 * DIM * DIM + 2 * DIM * SPAD) * (int)sizeof(float); // 67584
    cudaFuncSetAttribute(fused_layer_kernel, cudaFuncAttributeMaxDynamicSharedMemorySize, UPD_SMEM);

    // ---- One-time counting sort of edges by dst (CSR + packed records) ----
    zero_kernel<<<128, 256>>>((float4*)cnt, N_NODES / 4);
    hist_kernel<<<(N_EDGES + 255) / 256, 256>>>(dst);
    scan_sum_kernel<<<SCAN_NBLK, SCAN_B>>>();
    scan_tops_kernel<<<1, 128>>>();
    scan_write_kernel<<<SCAN_NBLK, SCAN_B>>>();
    reorder_kernel<<<(N_EDGES + 255) / 256, 256>>>(src, dst, a);

    // ---- Layers: fully fused, h read in-place from output tensor ----
    int grid = (N_NODES + 63) / 64;
    for (int l = 0; l < N_LAYERS; l++) {
        const float4* hin;
        int strideF4;
        if (l == 0) { hin = (const float4*)x; strideF4 = DIM / 4; }
        else        { hin = (const float4*)out + (size_t)l * (DIM / 4); strideF4 = OUT_DIM / 4; }
        fused_layer_kernel<<<grid, 256, UPD_SMEM>>>(
            hin, strideF4,
            W1s + (size_t)l * DIM * DIM, b1s + (size_t)l * DIM,
            W2s + (size_t)l * DIM * DIM, b2s + (size_t)l * DIM,
            out + (size_t)(l + 1) * DIM,
            (l == 0) ? out : nullptr);
    }
}

// round 7
// speedup vs baseline: 1.2534x; 1.0097x over previous
#include <cuda_runtime.h>
#include <cuda_bf16.h>

#define N_NODES 100000
#define N_EDGES 3200000
#define DIM 64
#define N_LAYERS 3
#define OUT_DIM (4 * DIM)

#define SCAN_B 1024
#define SCAN_NBLK ((N_NODES + SCAN_B - 1) / SCAN_B)   // 98
#define SPAD 68

// ---------------------------------------------------------------------------
// Scratch (allocation-free contract: __device__ globals)
// ---------------------------------------------------------------------------
__device__ int  g_count[N_NODES];            // per-dst degree histogram
__device__ int  g_cursor[N_NODES];           // running cursors for reorder
__device__ int  g_rowptr[N_NODES + 1];       // CSR offsets (dst-sorted)
__device__ int  g_blocksums[128];            // scan block sums
__device__ int2 g_sorted[N_EDGES];           // packed {src, a_bits}, dst-sorted

// ---------------------------------------------------------------------------
// Generic zero (float4-vectorized, grid-stride)
// ---------------------------------------------------------------------------
__global__ void zero_kernel(float4* __restrict__ p, int n4) {
    int i = blockIdx.x * blockDim.x + threadIdx.x;
    const float4 z = make_float4(0.f, 0.f, 0.f, 0.f);
    for (; i < n4; i += gridDim.x * blockDim.x) p[i] = z;
}

// ---------------------------------------------------------------------------
// Counting sort by dst (one-time)
// ---------------------------------------------------------------------------
__global__ void hist_kernel(const int* __restrict__ dst) {
    int e = blockIdx.x * blockDim.x + threadIdx.x;
    if (e >= N_EDGES) return;
    atomicAdd(&g_count[dst[e]], 1);
}

__global__ __launch_bounds__(SCAN_B)
void scan_sum_kernel() {
    int i = blockIdx.x * SCAN_B + threadIdx.x;
    int v = (i < N_NODES) ? g_count[i] : 0;
    int lane = threadIdx.x & 31, w = threadIdx.x >> 5;
    #pragma unroll
    for (int d = 16; d; d >>= 1) v += __shfl_down_sync(~0u, v, d);
    __shared__ int s[32];
    if (lane == 0) s[w] = v;
    __syncthreads();
    if (w == 0) {
        v = s[lane];
        #pragma unroll
        for (int d = 16; d; d >>= 1) v += __shfl_down_sync(~0u, v, d);
        if (lane == 0) g_blocksums[blockIdx.x] = v;
    }
}

__global__ void scan_tops_kernel() {
    __shared__ int s[128];
    int tid = threadIdx.x;
    int v = (tid < SCAN_NBLK) ? g_blocksums[tid] : 0;
    s[tid] = v;
    __syncthreads();
    for (int off = 1; off < 128; off <<= 1) {
        int t = (tid >= off) ? s[tid - off] : 0;
        __syncthreads();
        s[tid] += t;
        __syncthreads();
    }
    if (tid < SCAN_NBLK) g_blocksums[tid] = s[tid] - v;   // exclusive
    if (tid == 0) g_rowptr[N_NODES] = N_EDGES;
}

__global__ __launch_bounds__(SCAN_B)
void scan_write_kernel() {
    int i = blockIdx.x * SCAN_B + threadIdx.x;
    int v = (i < N_NODES) ? g_count[i] : 0;
    int lane = threadIdx.x & 31, w = threadIdx.x >> 5;
    int inc = v;
    #pragma unroll
    for (int d = 1; d < 32; d <<= 1) {
        int t = __shfl_up_sync(~0u, inc, d);
        if (lane >= d) inc += t;
    }
    __shared__ int ws[32];
    if (lane == 31) ws[w] = inc;
    __syncthreads();
    if (w == 0) {
        int t = ws[lane];
        #pragma unroll
        for (int d = 1; d < 32; d <<= 1) {
            int u = __shfl_up_sync(~0u, t, d);
            if (lane >= d) t += u;
        }
        ws[lane] = t;
    }
    __syncthreads();
    int warpOff = (w == 0) ? 0 : ws[w - 1];
    int excl = inc - v + warpOff + g_blocksums[blockIdx.x];
    if (i < N_NODES) { g_cursor[i] = excl; g_rowptr[i] = excl; }
}

__global__ void reorder_kernel(const int* __restrict__ src,
                               const int* __restrict__ dst,
                               const float* __restrict__ a) {
    int e = blockIdx.x * blockDim.x + threadIdx.x;
    if (e >= N_EDGES) return;
    int d = dst[e];
    int pos = atomicAdd(&g_cursor[d], 1);
    int2 rec;
    rec.x = src[e];
    rec.y = __float_as_int(a[e]);
    g_sorted[pos] = rec;
}

// ---------------------------------------------------------------------------
// Fused layer kernel (R4 gather loop + dynamic node scheduling):
//   Block owns 64 dst nodes. Half-warps claim nodes one at a time from a
//   shared counter (work stealing -> intra-block balance), gather+accumulate
//   the node's edge segment (register h_n, unroll-2), stage s/p transposed
//   in shared, then register-tiled dual GEMM + bias + lrelu + sum.
//   If copySeg != nullptr (layer 0): also writes h rows to out[:,0:64].
// ---------------------------------------------------------------------------
__device__ __forceinline__ float lrelu(float v) {
    return v > 0.f ? v : 0.01f * v;
}

extern __shared__ float dyn_smem[];

__global__ __launch_bounds__(256)
void fused_layer_kernel(const float4* __restrict__ hin, int strideF4,
                        const float* __restrict__ W1, const float* __restrict__ b1,
                        const float* __restrict__ W2, const float* __restrict__ b2,
                        float* __restrict__ outSeg,
                        float* __restrict__ copySeg) {
    float* sW1 = dyn_smem;                 // [64*64]
    float* sW2 = sW1 + DIM * DIM;          // [64*64]
    float* sS  = sW2 + DIM * DIM;          // [64][SPAD] k-major
    float* sP  = sS + DIM * SPAD;          // [64][SPAD]
    __shared__ int sCnt;

    int t = threadIdx.x;

    // Weights -> shared; init work counter
    {
        const float4* w1v = (const float4*)W1;
        const float4* w2v = (const float4*)W2;
        float4* s1v = (float4*)sW1;
        float4* s2v = (float4*)sW2;
        #pragma unroll
        for (int i = 0; i < 4; i++) {
            s1v[t + i * 256] = w1v[t + i * 256];
            s2v[t + i * 256] = w2v[t + i * 256];
        }
        if (t == 0) sCnt = 0;
    }
    __syncthreads();

    int base = blockIdx.x * 64;
    int lane = t & 15;      // float4-column within a 64-float row
    int lane32 = t & 31;
    int k0 = lane * 4;

    // Dynamic gather: half-warps claim nodes from shared counter.
    for (;;) {
        int nloc = 0;
        if (lane == 0) nloc = atomicAdd(&sCnt, 1);
        nloc = __shfl_sync(~0u, nloc, lane32 & 16);   // broadcast within half-warp
        if (nloc >= 64) break;

        int node = base + nloc;
        float4 acc = make_float4(0.f, 0.f, 0.f, 0.f);
        float4 hv  = make_float4(0.f, 0.f, 0.f, 0.f);
        if (node < N_NODES) {
            int e  = g_rowptr[node];
            int e1 = g_rowptr[node + 1];
            // unrolled by 2: two independent gathers in flight
            for (; e + 1 < e1; e += 2) {
                int2 r0 = g_sorted[e];
                int2 r1 = g_sorted[e + 1];
                float4 v0 = hin[(size_t)r0.x * strideF4 + lane];
                float4 v1 = hin[(size_t)r1.x * strideF4 + lane];
                float a0 = __int_as_float(r0.y);
                float a1 = __int_as_float(r1.y);
                acc.x = fmaf(a0, v0.x, acc.x);
                acc.y = fmaf(a0, v0.y, acc.y);
                acc.z = fmaf(a0, v0.z, acc.z);
                acc.w = fmaf(a0, v0.w, acc.w);
                acc.x = fmaf(a1, v1.x, acc.x);
                acc.y = fmaf(a1, v1.y, acc.y);
                acc.z = fmaf(a1, v1.z, acc.z);
                acc.w = fmaf(a1, v1.w, acc.w);
            }
            if (e < e1) {
                int2 r0 = g_sorted[e];
                float4 v0 = hin[(size_t)r0.x * strideF4 + lane];
                float a0 = __int_as_float(r0.y);
                acc.x = fmaf(a0, v0.x, acc.x);
                acc.y = fmaf(a0, v0.y, acc.y);
                acc.z = fmaf(a0, v0.z, acc.z);
                acc.w = fmaf(a0, v0.w, acc.w);
            }
            hv = hin[(size_t)node * strideF4 + lane];
            if (copySeg != nullptr)
                *(float4*)(copySeg + (size_t)node * OUT_DIM + k0) = hv;
        }
        // stage s = h + hn, p = h * hn, transposed [k][node]
        sS[(k0 + 0) * SPAD + nloc] = hv.x + acc.x;
        sS[(k0 + 1) * SPAD + nloc] = hv.y + acc.y;
        sS[(k0 + 2) * SPAD + nloc] = hv.z + acc.z;
        sS[(k0 + 3) * SPAD + nloc] = hv.w + acc.w;
        sP[(k0 + 0) * SPAD + nloc] = hv.x * acc.x;
        sP[(k0 + 1) * SPAD + nloc] = hv.y * acc.y;
        sP[(k0 + 2) * SPAD + nloc] = hv.z * acc.z;
        sP[(k0 + 3) * SPAD + nloc] = hv.w * acc.w;
    }
    __syncthreads();

    // Register-tiled dual GEMM: 4 nodes x 4 cols per thread
    int m0 = (t & 15) * 4;
    int c0 = (t >> 4) * 4;

    float acc1[4][4];
    float acc2[4][4];
    #pragma unroll
    for (int i = 0; i < 4; i++)
        #pragma unroll
        for (int j = 0; j < 4; j++) { acc1[i][j] = 0.f; acc2[i][j] = 0.f; }

    #pragma unroll 4
    for (int k = 0; k < DIM; k++) {
        float4 sv = *(const float4*)(sS + k * SPAD + m0);
        float4 pv = *(const float4*)(sP + k * SPAD + m0);
        float4 w1 = *(const float4*)(sW1 + k * DIM + c0);
        float4 w2 = *(const float4*)(sW2 + k * DIM + c0);
        float sm[4] = {sv.x, sv.y, sv.z, sv.w};
        float pm[4] = {pv.x, pv.y, pv.z, pv.w};
        float w1a[4] = {w1.x, w1.y, w1.z, w1.w};
        float w2a[4] = {w2.x, w2.y, w2.z, w2.w};
        #pragma unroll
        for (int i = 0; i < 4; i++) {
            #pragma unroll
            for (int j = 0; j < 4; j++) {
                acc1[i][j] = fmaf(sm[i], w1a[j], acc1[i][j]);
                acc2[i][j] = fmaf(pm[i], w2a[j], acc2[i][j]);
            }
        }
    }

    float4 rb1 = *(const float4*)(b1 + c0);
    float4 rb2 = *(const float4*)(b2 + c0);
    float b1a[4] = {rb1.x, rb1.y, rb1.z, rb1.w};
    float b2a[4] = {rb2.x, rb2.y, rb2.z, rb2.w};

    #pragma unroll
    for (int i = 0; i < 4; i++) {
        int node = base + m0 + i;
        if (node >= N_NODES) break;
        float4 r;
        float* rp = (float*)&r;
        #pragma unroll
        for (int j = 0; j < 4; j++)
            rp[j] = lrelu(acc1[i][j] + b1a[j]) + lrelu(acc2[i][j] + b2a[j]);
        *(float4*)(outSeg + (size_t)node * OUT_DIM + c0) = r;
    }
}

// ---------------------------------------------------------------------------
// Launch
// ---------------------------------------------------------------------------
extern "C" void kernel_launch(void* const* d_in, const int* in_sizes, int n_in,
                              void* d_out, int out_size) {
    const float* x   = (const float*)d_in[0];
    const float* a   = (const float*)d_in[1];
    const float* W1s = (const float*)d_in[2];
    const float* b1s = (const float*)d_in[3];
    const float* W2s = (const float*)d_in[4];
    const float* b2s = (const float*)d_in[5];
    const int*   src = (const int*)d_in[6];
    const int*   dst = (const int*)d_in[7];
    float* out = (float*)d_out;

    int* cnt;
    cudaGetSymbolAddress((void**)&cnt, g_count);

    const int UPD_SMEM = (2 * DIM * DIM + 2 * DIM * SPAD) * (int)sizeof(float); // 67584
    cudaFuncSetAttribute(fused_layer_kernel, cudaFuncAttributeMaxDynamicSharedMemorySize, UPD_SMEM);

    // ---- One-time counting sort of edges by dst (CSR + packed records) ----
    zero_kernel<<<128, 256>>>((float4*)cnt, N_NODES / 4);
    hist_kernel<<<(N_EDGES + 255) / 256, 256>>>(dst);
    scan_sum_kernel<<<SCAN_NBLK, SCAN_B>>>();
    scan_tops_kernel<<<1, 128>>>();
    scan_write_kernel<<<SCAN_NBLK, SCAN_B>>>();
    reorder_kernel<<<(N_EDGES + 255) / 256, 256>>>(src, dst, a);

    // ---- Layers: fully fused, h read in-place from output tensor ----
    int grid = (N_NODES + 63) / 64;
    for (int l = 0; l < N_LAYERS; l++) {
        const float4* hin;
        int strideF4;
        if (l == 0) { hin = (const float4*)x; strideF4 = DIM / 4; }
        else        { hin = (const float4*)out + (size_t)l * (DIM / 4); strideF4 = OUT_DIM / 4; }
        fused_layer_kernel<<<grid, 256, UPD_SMEM>>>(
            hin, strideF4,
            W1s + (size_t)l * DIM * DIM, b1s + (size_t)l * DIM,
            W2s + (size_t)l * DIM * DIM, b2s + (size_t)l * DIM,
            out + (size_t)(l + 1) * DIM,
            (l == 0) ? out : nullptr);
    }
}

// round 8
// speedup vs baseline: 1.2578x; 1.0036x over previous
#include <cuda_runtime.h>
#include <cuda_bf16.h>

#define N_NODES 100000
#define N_EDGES 3200000
#define DIM 64
#define N_LAYERS 3
#define OUT_DIM (4 * DIM)

#define SCAN_B 1024
#define SCAN_NBLK ((N_NODES + SCAN_B - 1) / SCAN_B)   // 98

#define TILE_N 128          // nodes per block
#define BLK_T  512          // threads per block
#define SPAD 132            // staging row stride (128 + 4)

// ---------------------------------------------------------------------------
// Scratch (allocation-free contract: __device__ globals)
// ---------------------------------------------------------------------------
__device__ int  g_count[N_NODES];            // per-dst degree histogram
__device__ int  g_cursor[N_NODES];           // running cursors for reorder
__device__ int  g_rowptr[N_NODES + 1];       // CSR offsets (dst-sorted)
__device__ int  g_blocksums[128];            // scan block sums
__device__ int2 g_sorted[N_EDGES];           // packed {src, a_bits}, dst-sorted

// ---------------------------------------------------------------------------
// Generic zero (float4-vectorized, grid-stride)
// ---------------------------------------------------------------------------
__global__ void zero_kernel(float4* __restrict__ p, int n4) {
    int i = blockIdx.x * blockDim.x + threadIdx.x;
    const float4 z = make_float4(0.f, 0.f, 0.f, 0.f);
    for (; i < n4; i += gridDim.x * blockDim.x) p[i] = z;
}

// ---------------------------------------------------------------------------
// Copy x into out[:, 0:64]
// ---------------------------------------------------------------------------
__global__ void copy_x_kernel(const float4* __restrict__ x4, float4* __restrict__ out4) {
    int i = blockIdx.x * blockDim.x + threadIdx.x;
    if (i >= N_NODES * (DIM / 4)) return;
    int n = i >> 4;
    int c = i & 15;
    out4[n * (OUT_DIM / 4) + c] = x4[i];
}

// ---------------------------------------------------------------------------
// Counting sort by dst (one-time)
// ---------------------------------------------------------------------------
__global__ void hist_kernel(const int* __restrict__ dst) {
    int e = blockIdx.x * blockDim.x + threadIdx.x;
    if (e >= N_EDGES) return;
    atomicAdd(&g_count[dst[e]], 1);
}

__global__ __launch_bounds__(SCAN_B)
void scan_sum_kernel() {
    int i = blockIdx.x * SCAN_B + threadIdx.x;
    int v = (i < N_NODES) ? g_count[i] : 0;
    int lane = threadIdx.x & 31, w = threadIdx.x >> 5;
    #pragma unroll
    for (int d = 16; d; d >>= 1) v += __shfl_down_sync(~0u, v, d);
    __shared__ int s[32];
    if (lane == 0) s[w] = v;
    __syncthreads();
    if (w == 0) {
        v = s[lane];
        #pragma unroll
        for (int d = 16; d; d >>= 1) v += __shfl_down_sync(~0u, v, d);
        if (lane == 0) g_blocksums[blockIdx.x] = v;
    }
}

__global__ void scan_tops_kernel() {
    __shared__ int s[128];
    int tid = threadIdx.x;
    int v = (tid < SCAN_NBLK) ? g_blocksums[tid] : 0;
    s[tid] = v;
    __syncthreads();
    for (int off = 1; off < 128; off <<= 1) {
        int t = (tid >= off) ? s[tid - off] : 0;
        __syncthreads();
        s[tid] += t;
        __syncthreads();
    }
    if (tid < SCAN_NBLK) g_blocksums[tid] = s[tid] - v;   // exclusive
    if (tid == 0) g_rowptr[N_NODES] = N_EDGES;
}

__global__ __launch_bounds__(SCAN_B)
void scan_write_kernel() {
    int i = blockIdx.x * SCAN_B + threadIdx.x;
    int v = (i < N_NODES) ? g_count[i] : 0;
    int lane = threadIdx.x & 31, w = threadIdx.x >> 5;
    int inc = v;
    #pragma unroll
    for (int d = 1; d < 32; d <<= 1) {
        int t = __shfl_up_sync(~0u, inc, d);
        if (lane >= d) inc += t;
    }
    __shared__ int ws[32];
    if (lane == 31) ws[w] = inc;
    __syncthreads();
    if (w == 0) {
        int t = ws[lane];
        #pragma unroll
        for (int d = 1; d < 32; d <<= 1) {
            int u = __shfl_up_sync(~0u, t, d);
            if (lane >= d) t += u;
        }
        ws[lane] = t;
    }
    __syncthreads();
    int warpOff = (w == 0) ? 0 : ws[w - 1];
    int excl = inc - v + warpOff + g_blocksums[blockIdx.x];
    if (i < N_NODES) { g_cursor[i] = excl; g_rowptr[i] = excl; }
}

__global__ void reorder_kernel(const int* __restrict__ src,
                               const int* __restrict__ dst,
                               const float* __restrict__ a) {
    int e = blockIdx.x * blockDim.x + threadIdx.x;
    if (e >= N_EDGES) return;
    int d = dst[e];
    int pos = atomicAdd(&g_cursor[d], 1);
    int2 rec;
    rec.x = src[e];
    rec.y = __float_as_int(a[e]);
    g_sorted[pos] = rec;
}

// ---------------------------------------------------------------------------
// Fused layer kernel (R4 structure, 512 threads / 128-node tiles):
//   32 half-warps each gather+accumulate 4 nodes' edge segments (register
//   h_n, unroll-2), stage s/p transposed in shared, then register-tiled dual
//   GEMM (4 nodes x 4 cols x 2 mats per thread) + bias + lrelu + sum.
// ---------------------------------------------------------------------------
__device__ __forceinline__ float lrelu(float v) {
    return v > 0.f ? v : 0.01f * v;
}

extern __shared__ float dyn_smem[];

__global__ __launch_bounds__(BLK_T, 2)
void fused_layer_kernel(const float4* __restrict__ hin, int strideF4,
                        const float* __restrict__ W1, const float* __restrict__ b1,
                        const float* __restrict__ W2, const float* __restrict__ b2,
                        float* __restrict__ outSeg) {
    float* sW1 = dyn_smem;                 // [64*64]
    float* sW2 = sW1 + DIM * DIM;          // [64*64]
    float* sS  = sW2 + DIM * DIM;          // [64][SPAD] k-major
    float* sP  = sS + DIM * SPAD;          // [64][SPAD]

    int t = threadIdx.x;

    // Weights -> shared (1024 float4 each, 512 threads -> 2 iters)
    {
        const float4* w1v = (const float4*)W1;
        const float4* w2v = (const float4*)W2;
        float4* s1v = (float4*)sW1;
        float4* s2v = (float4*)sW2;
        #pragma unroll
        for (int i = 0; i < 2; i++) {
            s1v[t + i * BLK_T] = w1v[t + i * BLK_T];
            s2v[t + i * BLK_T] = w2v[t + i * BLK_T];
        }
    }

    int base = blockIdx.x * TILE_N;
    int hw = t >> 4;        // half-warp id 0..31
    int lane = t & 15;      // float4-column within a 64-float row
    int k0 = lane * 4;

    // Gather + accumulate + stage. Each half-warp owns 4 consecutive nodes.
    #pragma unroll
    for (int i = 0; i < 4; i++) {
        int nloc = hw * 4 + i;
        int node = base + nloc;
        float4 acc = make_float4(0.f, 0.f, 0.f, 0.f);
        float4 hv  = make_float4(0.f, 0.f, 0.f, 0.f);
        if (node < N_NODES) {
            int e  = g_rowptr[node];
            int e1 = g_rowptr[node + 1];
            // unrolled by 2: two independent gathers in flight
            for (; e + 1 < e1; e += 2) {
                int2 r0 = g_sorted[e];
                int2 r1 = g_sorted[e + 1];
                float4 v0 = hin[(size_t)r0.x * strideF4 + lane];
                float4 v1 = hin[(size_t)r1.x * strideF4 + lane];
                float a0 = __int_as_float(r0.y);
                float a1 = __int_as_float(r1.y);
                acc.x = fmaf(a0, v0.x, acc.x);
                acc.y = fmaf(a0, v0.y, acc.y);
                acc.z = fmaf(a0, v0.z, acc.z);
                acc.w = fmaf(a0, v0.w, acc.w);
                acc.x = fmaf(a1, v1.x, acc.x);
                acc.y = fmaf(a1, v1.y, acc.y);
                acc.z = fmaf(a1, v1.z, acc.z);
                acc.w = fmaf(a1, v1.w, acc.w);
            }
            if (e < e1) {
                int2 r0 = g_sorted[e];
                float4 v0 = hin[(size_t)r0.x * strideF4 + lane];
                float a0 = __int_as_float(r0.y);
                acc.x = fmaf(a0, v0.x, acc.x);
                acc.y = fmaf(a0, v0.y, acc.y);
                acc.z = fmaf(a0, v0.z, acc.z);
                acc.w = fmaf(a0, v0.w, acc.w);
            }
            hv = hin[(size_t)node * strideF4 + lane];
        }
        // stage s = h + hn, p = h * hn, transposed [k][node]
        sS[(k0 + 0) * SPAD + nloc] = hv.x + acc.x;
        sS[(k0 + 1) * SPAD + nloc] = hv.y + acc.y;
        sS[(k0 + 2) * SPAD + nloc] = hv.z + acc.z;
        sS[(k0 + 3) * SPAD + nloc] = hv.w + acc.w;
        sP[(k0 + 0) * SPAD + nloc] = hv.x * acc.x;
        sP[(k0 + 1) * SPAD + nloc] = hv.y * acc.y;
        sP[(k0 + 2) * SPAD + nloc] = hv.z * acc.z;
        sP[(k0 + 3) * SPAD + nloc] = hv.w * acc.w;
    }
    __syncthreads();

    // Register-tiled dual GEMM: 4 nodes x 4 cols per thread
    int m0 = (t & 31) * 4;     // node offset within 128-node tile
    int c0 = (t >> 5) * 4;     // col offset 0..60

    float acc1[4][4];
    float acc2[4][4];
    #pragma unroll
    for (int i = 0; i < 4; i++)
        #pragma unroll
        for (int j = 0; j < 4; j++) { acc1[i][j] = 0.f; acc2[i][j] = 0.f; }

    #pragma unroll 4
    for (int k = 0; k < DIM; k++) {
        float4 sv = *(const float4*)(sS + k * SPAD + m0);
        float4 pv = *(const float4*)(sP + k * SPAD + m0);
        float4 w1 = *(const float4*)(sW1 + k * DIM + c0);
        float4 w2 = *(const float4*)(sW2 + k * DIM + c0);
        float sm[4] = {sv.x, sv.y, sv.z, sv.w};
        float pm[4] = {pv.x, pv.y, pv.z, pv.w};
        float w1a[4] = {w1.x, w1.y, w1.z, w1.w};
        float w2a[4] = {w2.x, w2.y, w2.z, w2.w};
        #pragma unroll
        for (int i = 0; i < 4; i++) {
            #pragma unroll
            for (int j = 0; j < 4; j++) {
                acc1[i][j] = fmaf(sm[i], w1a[j], acc1[i][j]);
                acc2[i][j] = fmaf(pm[i], w2a[j], acc2[i][j]);
            }
        }
    }

    float4 rb1 = *(const float4*)(b1 + c0);
    float4 rb2 = *(const float4*)(b2 + c0);
    float b1a[4] = {rb1.x, rb1.y, rb1.z, rb1.w};
    float b2a[4] = {rb2.x, rb2.y, rb2.z, rb2.w};

    #pragma unroll
    for (int i = 0; i < 4; i++) {
        int node = base + m0 + i;
        if (node >= N_NODES) break;
        float4 r;
        float* rp = (float*)&r;
        #pragma unroll
        for (int j = 0; j < 4; j++)
            rp[j] = lrelu(acc1[i][j] + b1a[j]) + lrelu(acc2[i][j] + b2a[j]);
        *(float4*)(outSeg + (size_t)node * OUT_DIM + c0) = r;
    }
}

// ---------------------------------------------------------------------------
// Launch
// ---------------------------------------------------------------------------
extern "C" void kernel_launch(void* const* d_in, const int* in_sizes, int n_in,
                              void* d_out, int out_size) {
    const float* x   = (const float*)d_in[0];
    const float* a   = (const float*)d_in[1];
    const float* W1s = (const float*)d_in[2];
    const float* b1s = (const float*)d_in[3];
    const float* W2s = (const float*)d_in[4];
    const float* b2s = (const float*)d_in[5];
    const int*   src = (const int*)d_in[6];
    const int*   dst = (const int*)d_in[7];
    float* out = (float*)d_out;

    int* cnt;
    cudaGetSymbolAddress((void**)&cnt, g_count);

    const int UPD_SMEM = (2 * DIM * DIM + 2 * DIM * SPAD) * (int)sizeof(float); // 100352
    cudaFuncSetAttribute(fused_layer_kernel, cudaFuncAttributeMaxDynamicSharedMemorySize, UPD_SMEM);

    // out[:, 0:64] = x
    {
        int n4 = N_NODES * (DIM / 4);
        copy_x_kernel<<<(n4 + 255) / 256, 256>>>((const float4*)x, (float4*)out);
    }

    // ---- One-time counting sort of edges by dst (CSR + packed records) ----
    zero_kernel<<<128, 256>>>((float4*)cnt, N_NODES / 4);
    hist_kernel<<<(N_EDGES + 255) / 256, 256>>>(dst);
    scan_sum_kernel<<<SCAN_NBLK, SCAN_B>>>();
    scan_tops_kernel<<<1, 128>>>();
    scan_write_kernel<<<SCAN_NBLK, SCAN_B>>>();
    reorder_kernel<<<(N_EDGES + 255) / 256, 256>>>(src, dst, a);

    // ---- Layers: fully fused, h read in-place from output tensor ----
    int grid = (N_NODES + TILE_N - 1) / TILE_N;
    for (int l = 0; l < N_LAYERS; l++) {
        const float4* hin;
        int strideF4;
        if (l == 0) { hin = (const float4*)x; strideF4 = DIM / 4; }
        else        { hin = (const float4*)out + (size_t)l * (DIM / 4); strideF4 = OUT_DIM / 4; }
        fused_layer_kernel<<<grid, BLK_T, UPD_SMEM>>>(
            hin, strideF4,
            W1s + (size_t)l * DIM * DIM, b1s + (size_t)l * DIM,
            W2s + (size_t)l * DIM * DIM, b2s + (size_t)l * DIM,
            out + (size_t)(l + 1) * DIM);
    }
}